// round 1
// baseline (speedup 1.0000x reference)
#include <cuda_runtime.h>
#include <math.h>

// ---------------- problem constants ----------------
#define B_    256
#define C_    1024
#define S_    49
#define D_    1024
#define L_    2
#define H_    2
#define HD_   512
#define FF_   1024
#define OUT_  1024
#define M_    (B_ * S_)   // 12544 rows

// ---------------- device scratch (no allocs allowed) ----------------
__device__ float g_h [M_ * D_];
__device__ float g_hn[M_ * D_];
__device__ float g_q [M_ * D_];
__device__ float g_k [M_ * D_];
__device__ float g_v [M_ * D_];

// ---------------- embed: [B,C,7,7] -> [B,S,D] + pos ----------------
__global__ void embed_kernel(const float* __restrict__ x, const float* __restrict__ pos) {
    __shared__ float tile[64][S_ + 1];
    int b  = blockIdx.y;
    int d0 = blockIdx.x * 64;
    int tid = threadIdx.x;
    for (int idx = tid; idx < 64 * S_; idx += 256) {
        int dr = idx / S_, s = idx % S_;
        tile[dr][s] = x[(size_t)(b * C_ + d0 + dr) * S_ + s];
    }
    __syncthreads();
    for (int idx = tid; idx < S_ * 64; idx += 256) {
        int s = idx >> 6, dr = idx & 63;
        g_h[(size_t)(b * S_ + s) * D_ + d0 + dr] = tile[dr][s] + pos[s * D_ + d0 + dr];
    }
}

// ---------------- layernorm: one block per row, D=1024 ----------------
__global__ void ln_kernel(const float* __restrict__ in, float* __restrict__ out,
                          const float* __restrict__ sc, const float* __restrict__ bi) {
    int row = blockIdx.x;
    const float* p = in + (size_t)row * D_;
    int tid = threadIdx.x;
    float v[4];
    float s = 0.f, ss = 0.f;
#pragma unroll
    for (int i = 0; i < 4; i++) {
        float t = p[tid + i * 256];
        v[i] = t; s += t; ss += t * t;
    }
    __shared__ float rs[8], rss[8];
    int lane = tid & 31, w = tid >> 5;
#pragma unroll
    for (int o = 16; o; o >>= 1) {
        s  += __shfl_xor_sync(0xffffffffu, s,  o);
        ss += __shfl_xor_sync(0xffffffffu, ss, o);
    }
    if (lane == 0) { rs[w] = s; rss[w] = ss; }
    __syncthreads();
    if (tid < 32) {
        float s2  = (tid < 8) ? rs[tid]  : 0.f;
        float ss2 = (tid < 8) ? rss[tid] : 0.f;
#pragma unroll
        for (int o = 4; o; o >>= 1) {
            s2  += __shfl_xor_sync(0xffffffffu, s2,  o);
            ss2 += __shfl_xor_sync(0xffffffffu, ss2, o);
        }
        if (tid == 0) { rs[0] = s2; rss[0] = ss2; }
    }
    __syncthreads();
    float mean = rs[0] * (1.f / 1024.f);
    float var  = rss[0] * (1.f / 1024.f) - mean * mean;
    float inv  = rsqrtf(var + 1e-5f);
#pragma unroll
    for (int i = 0; i < 4; i++) {
        int d = tid + i * 256;
        out[(size_t)row * D_ + d] = (v[i] - mean) * inv * sc[d] + bi[d];
    }
}

// ---------------- gelu_new ----------------
__device__ __forceinline__ float gelu_new(float x) {
    float x3 = x * x * x;
    return 0.5f * x * (1.f + tanhf(0.7978845608028654f * (x + 0.044715f * x3)));
}

// ---------------- templated SGEMM C = A[MxK] @ W[KxN] with epilogue ----------------
// EPI: 0 = none, 1 = +R, 2 = +bias,gelu, 3 = +bias,relu, 4 = +bias +R
template<int BM, int BN, int BK, int TM, int TN, int EPI>
__global__ void sgemm_kernel(const float* __restrict__ A, const float* __restrict__ W,
                             const float* __restrict__ bias, const float* __restrict__ R,
                             float* __restrict__ C, int M, int N, int K) {
    constexpr int NT = (BM / TM) * (BN / TN);  // 256
    __shared__ float As[BK][BM];
    __shared__ float Bs[BK][BN];
    int tid = threadIdx.x;
    int bm = blockIdx.y, bn = blockIdx.x;
    const float* Ab = A + (size_t)bm * BM * K;
    const float* Wb = W + (size_t)bn * BN;
    float acc[TM][TN];
#pragma unroll
    for (int m = 0; m < TM; m++)
#pragma unroll
        for (int n = 0; n < TN; n++) acc[m][n] = 0.f;

    int tr = tid / (BN / TN);
    int tc = tid % (BN / TN);
    constexpr int A4 = BM * BK / (NT * 4);
    constexpr int B4 = BK * BN / (NT * 4);

    for (int k0 = 0; k0 < K; k0 += BK) {
#pragma unroll
        for (int i = 0; i < A4; i++) {
            int idx4 = tid + i * NT;
            int r = idx4 / (BK / 4);
            int c4 = (idx4 % (BK / 4)) * 4;
            float4 t = *(const float4*)(Ab + (size_t)r * K + k0 + c4);
            As[c4 + 0][r] = t.x; As[c4 + 1][r] = t.y;
            As[c4 + 2][r] = t.z; As[c4 + 3][r] = t.w;
        }
#pragma unroll
        for (int i = 0; i < B4; i++) {
            int idx4 = tid + i * NT;
            int r = idx4 / (BN / 4);
            int c4 = (idx4 % (BN / 4)) * 4;
            *(float4*)(&Bs[r][c4]) = *(const float4*)(Wb + (size_t)(k0 + r) * N + c4);
        }
        __syncthreads();
#pragma unroll
        for (int kk = 0; kk < BK; kk++) {
            float ra[TM], rb[TN];
#pragma unroll
            for (int m = 0; m < TM; m++) ra[m] = As[kk][tr * TM + m];
#pragma unroll
            for (int n = 0; n < TN; n++) rb[n] = Bs[kk][tc * TN + n];
#pragma unroll
            for (int m = 0; m < TM; m++)
#pragma unroll
                for (int n = 0; n < TN; n++) acc[m][n] += ra[m] * rb[n];
        }
        __syncthreads();
    }

#pragma unroll
    for (int m = 0; m < TM; m++) {
        int row = bm * BM + tr * TM + m;
#pragma unroll
        for (int n = 0; n < TN; n++) {
            int col = bn * BN + tc * TN + n;
            float v = acc[m][n];
            if (EPI == 1) v += R[(size_t)row * N + col];
            if (EPI == 2) { v += bias[col]; v = gelu_new(v); }
            if (EPI == 3) { v += bias[col]; v = fmaxf(v, 0.f); }
            if (EPI == 4) { v += bias[col] + R[(size_t)row * N + col]; }
            C[(size_t)row * N + col] = v;
        }
    }
}

// ---------------- fused attention: one block per (b, head) ----------------
// scores = (Q @ K^T) * scale ; softmax ; ctx = attn @ V   (S=49, HD=512)
__global__ void attn_kernel() {
    int bh = blockIdx.x;
    int b  = bh >> 1;
    int hh = bh & 1;
    __shared__ float qs[S_ * 65];
    __shared__ float ks[S_ * 65];   // reused for V
    __shared__ float sc[S_ * 50];
    int tid = threadIdx.x;

    int qidx[10], kidx[10];
    float acc[10];
#pragma unroll
    for (int j = 0; j < 10; j++) {
        int p = tid + j * 256;
        acc[j] = 0.f;
        qidx[j] = (p < 2401) ? (p / 49) : 0;
        kidx[j] = (p < 2401) ? (p % 49) : 0;
    }

    const size_t base = (size_t)b * S_ * D_ + hh * HD_;

    // scores accumulation over 8 chunks of 64 head-dims
    for (int c = 0; c < 8; c++) {
        for (int idx = tid; idx < S_ * 64; idx += 256) {
            int r = idx >> 6, d = idx & 63;
            qs[r * 65 + d] = g_q[base + (size_t)r * D_ + c * 64 + d];
            ks[r * 65 + d] = g_k[base + (size_t)r * D_ + c * 64 + d];
        }
        __syncthreads();
#pragma unroll
        for (int j = 0; j < 10; j++) {
            if (tid + j * 256 < 2401) {
                const float* qp = &qs[qidx[j] * 65];
                const float* kp = &ks[kidx[j] * 65];
                float s = 0.f;
#pragma unroll
                for (int d = 0; d < 64; d++) s += qp[d] * kp[d];
                acc[j] += s;
            }
        }
        __syncthreads();
    }

    const float scale = 0.044194173824159216f;  // 1/sqrt(512)
#pragma unroll
    for (int j = 0; j < 10; j++) {
        if (tid + j * 256 < 2401) sc[qidx[j] * 50 + kidx[j]] = acc[j] * scale;
    }
    __syncthreads();

    // softmax per row (49 rows, thread t handles row t)
    if (tid < S_) {
        float mx = -1e30f;
        for (int k = 0; k < S_; k++) mx = fmaxf(mx, sc[tid * 50 + k]);
        float sum = 0.f;
        for (int k = 0; k < S_; k++) {
            float e = __expf(sc[tid * 50 + k] - mx);
            sc[tid * 50 + k] = e; sum += e;
        }
        float inv = 1.f / sum;
        for (int k = 0; k < S_; k++) sc[tid * 50 + k] *= inv;
    }
    __syncthreads();

    // ctx = attn @ V, chunked over head-dim; write into g_hn
    for (int c = 0; c < 8; c++) {
        for (int idx = tid; idx < S_ * 64; idx += 256) {
            int r = idx >> 6, d = idx & 63;
            ks[r * 65 + d] = g_v[base + (size_t)r * D_ + c * 64 + d];
        }
        __syncthreads();
        for (int idx = tid; idx < S_ * 64; idx += 256) {
            int q = idx >> 6, d = idx & 63;
            float s = 0.f;
#pragma unroll
            for (int k = 0; k < S_; k++) s += sc[q * 50 + k] * ks[k * 65 + d];
            g_hn[base + (size_t)q * D_ + c * 64 + d] = s;
        }
        __syncthreads();
    }
}

// ---------------- host orchestration ----------------
extern "C" void kernel_launch(void* const* d_in, const int* in_sizes, int n_in,
                              void* d_out, int out_size) {
    (void)in_sizes; (void)n_in; (void)out_size;
    const float* x      = (const float*)d_in[0];
    const float* pos    = (const float*)d_in[1];
    const float* ln1_s  = (const float*)d_in[2];
    const float* ln1_b  = (const float*)d_in[3];
    const float* wq     = (const float*)d_in[4];
    const float* wk     = (const float*)d_in[5];
    const float* wv     = (const float*)d_in[6];
    const float* wo     = (const float*)d_in[7];
    const float* ln2_s  = (const float*)d_in[8];
    const float* ln2_b  = (const float*)d_in[9];
    const float* w1     = (const float*)d_in[10];
    const float* b1     = (const float*)d_in[11];
    const float* w2     = (const float*)d_in[12];
    const float* b2     = (const float*)d_in[13];
    const float* lnf_s  = (const float*)d_in[14];
    const float* lnf_b  = (const float*)d_in[15];
    const float* head_w = (const float*)d_in[16];
    const float* head_b = (const float*)d_in[17];
    float* out = (float*)d_out;

    float *pH, *pHn, *pQ, *pK, *pV;
    cudaGetSymbolAddress((void**)&pH,  g_h);
    cudaGetSymbolAddress((void**)&pHn, g_hn);
    cudaGetSymbolAddress((void**)&pQ,  g_q);
    cudaGetSymbolAddress((void**)&pK,  g_k);
    cudaGetSymbolAddress((void**)&pV,  g_v);

    const dim3 gBig(D_ / 128, M_ / 128);   // 8 x 98
    const int WSZ = D_ * D_;               // per-layer weight stride

    embed_kernel<<<dim3(D_ / 64, B_), 256>>>(x, pos);

    for (int i = 0; i < L_; i++) {
        // pre-LN 1
        ln_kernel<<<M_, 256>>>(pH, pHn, ln1_s + i * D_, ln1_b + i * D_);
        // Q,K,V projections
        sgemm_kernel<128,128,8,8,8,0><<<gBig, 256>>>(pHn, wq + (size_t)i * WSZ, nullptr, nullptr, pQ, M_, D_, D_);
        sgemm_kernel<128,128,8,8,8,0><<<gBig, 256>>>(pHn, wk + (size_t)i * WSZ, nullptr, nullptr, pK, M_, D_, D_);
        sgemm_kernel<128,128,8,8,8,0><<<gBig, 256>>>(pHn, wv + (size_t)i * WSZ, nullptr, nullptr, pV, M_, D_, D_);
        // fused attention (writes ctx into g_hn)
        attn_kernel<<<B_ * H_, 256>>>();
        // out projection + residual (in-place on g_h)
        sgemm_kernel<128,128,8,8,8,1><<<gBig, 256>>>(pHn, wo + (size_t)i * WSZ, nullptr, pH, pH, M_, D_, D_);
        // pre-LN 2
        ln_kernel<<<M_, 256>>>(pH, pHn, ln2_s + i * D_, ln2_b + i * D_);
        // FF1: gelu(hn @ w1 + b1) -> g_q (reuse)
        sgemm_kernel<128,128,8,8,8,2><<<gBig, 256>>>(pHn, w1 + (size_t)i * WSZ, b1 + i * FF_, nullptr, pQ, M_, FF_, D_);
        // FF2: h += t @ w2 + b2 (in-place on g_h)
        sgemm_kernel<128,128,8,8,8,4><<<gBig, 256>>>(pQ, w2 + (size_t)i * WSZ, b2 + i * D_, pH, pH, M_, D_, FF_);
    }

    // final LN
    ln_kernel<<<M_, 256>>>(pH, pHn, lnf_s, lnf_b);

    // head: [256, 50176] @ [50176, 1024] + bias, relu
    sgemm_kernel<64,64,16,4,4,3><<<dim3(OUT_ / 64, B_ / 64), 256>>>(
        pHn, head_w, head_b, nullptr, out, B_, OUT_, S_ * D_);
}

// round 3
// speedup vs baseline: 2.5948x; 2.5948x over previous
#include <cuda_runtime.h>
#include <cuda_bf16.h>
#include <math.h>
#include <cstdint>

// ---------------- problem constants ----------------
#define B_    256
#define C_    1024
#define S_    49
#define D_    1024
#define L_    2
#define H_    2
#define HD_   512
#define FF_   1024
#define OUT_  1024
#define M_    (B_ * S_)   // 12544 rows
#define KHEAD (S_ * D_)   // 50176

// ---------------- device scratch (no allocs allowed) ----------------
__device__ float g_h [M_ * D_];
__device__ float g_hn[M_ * D_];
__device__ float g_q [M_ * D_];
__device__ float g_k [M_ * D_];
__device__ float g_v [M_ * D_];
__device__ __nv_bfloat16 g_ah[M_ * D_];
__device__ __nv_bfloat16 g_al[M_ * D_];
__device__ __nv_bfloat16 g_wh[12 * D_ * D_];   // transposed encoder weights hi
__device__ __nv_bfloat16 g_wl[12 * D_ * D_];   // transposed encoder weights lo
__device__ __nv_bfloat16 g_hwh[OUT_ * KHEAD];  // transposed head weight hi
__device__ __nv_bfloat16 g_hwl[OUT_ * KHEAD];  // transposed head weight lo
__device__ float g_part[16 * B_ * OUT_];       // head split-K partials

// ---------------- gelu_new ----------------
__device__ __forceinline__ float gelu_new(float x) {
    float x3 = x * x * x;
    return 0.5f * x * (1.f + tanhf(0.7978845608028654f * (x + 0.044715f * x3)));
}

// ================= mma.sync bf16 split GEMM =================
// C[M x N] = A @ W, A split hi/lo bf16 [rows, ld], W transposed [N, ld] hi/lo.
// Tile: 128x128x32, 256 threads, warp grid 2(m) x 4(n), warp tile 64x32.
// EPI: 0 none, 1 +R, 2 bias+gelu, 4 bias+R
#define PADB   80                         // smem row stride bytes (32 bf16 = 64B data)
#define MATB   (128 * PADB)               // 10240 per matrix tile
#define STAGEB (4 * MATB)                 // Ah, Al, Bh, Bl
#define SMEM_GEMM (2 * STAGEB)            // 81920

__device__ __forceinline__ void mma16816(float* d, const uint32_t* a, const uint32_t* b) {
    asm volatile(
        "mma.sync.aligned.m16n8k16.row.col.f32.bf16.bf16.f32 "
        "{%0,%1,%2,%3}, {%4,%5,%6,%7}, {%8,%9}, {%0,%1,%2,%3};"
        : "+f"(d[0]), "+f"(d[1]), "+f"(d[2]), "+f"(d[3])
        : "r"(a[0]), "r"(a[1]), "r"(a[2]), "r"(a[3]), "r"(b[0]), "r"(b[1]));
}

template<int EPI>
__global__ __launch_bounds__(256, 1) void mma_gemm(
    const __nv_bfloat16* __restrict__ Ah, const __nv_bfloat16* __restrict__ Al,
    const __nv_bfloat16* __restrict__ Bh, const __nv_bfloat16* __restrict__ Bl,
    const float* __restrict__ bias, const float* __restrict__ R, float* __restrict__ C,
    int ld, int kIters, int ldc, int zStride)
{
    extern __shared__ char smem[];
    int tid = threadIdx.x, wid = tid >> 5, lane = tid & 31;
    int bn = blockIdx.x, bm = blockIdx.y, bz = blockIdx.z;
    size_t kStart = (size_t)bz * kIters * 32;

    // ---- loader setup: thread -> (matrix, rowb, seg) ----
    int tmat = tid >> 6;        // 0:Ah 1:Al 2:Bh 3:Bl
    int tt = tid & 63;
    int seg = tt & 3;           // 16B segment in 64B row
    int rowb = tt >> 2;         // 0..15
    const __nv_bfloat16* mbase[4] = {
        Ah + (size_t)bm * 128 * ld,
        Al + (size_t)bm * 128 * ld,
        Bh + (size_t)bn * 128 * ld,
        Bl + (size_t)bn * 128 * ld };
    const __nv_bfloat16* gb = mbase[tmat] + (size_t)rowb * ld + kStart + seg * 8;
    char* sdst = smem + tmat * MATB + rowb * PADB + seg * 16;
    const size_t rstep = (size_t)16 * ld;

#define LOAD_STAGE(stg, kpos)                                                     \
    {                                                                             \
        const __nv_bfloat16* s = gb + (kpos);                                     \
        char* dd = sdst + (stg) * STAGEB;                                         \
        _Pragma("unroll")                                                         \
        for (int rr = 0; rr < 8; rr++) {                                          \
            uint32_t da;                                                          \
            asm("{ .reg .u64 t; cvta.to.shared.u64 t, %1; cvt.u32.u64 %0, t; }"   \
                : "=r"(da) : "l"(dd + rr * 16 * PADB));                           \
            asm volatile("cp.async.cg.shared.global [%0], [%1], 16;"              \
                         :: "r"(da), "l"(s + rr * rstep) : "memory");             \
        }                                                                         \
        asm volatile("cp.async.commit_group;" ::: "memory");                      \
    }

    // ---- compute setup ----
    int warp_m = wid >> 2, warp_n = wid & 3;
    int g = lane >> 2, tg = lane & 3;
    float acc[4][4][4];
#pragma unroll
    for (int mt = 0; mt < 4; mt++)
#pragma unroll
        for (int nt = 0; nt < 4; nt++)
#pragma unroll
            for (int j = 0; j < 4; j++) acc[mt][nt][j] = 0.f;

    LOAD_STAGE(0, 0);

    for (int it = 0; it < kIters; it++) {
        if (it + 1 < kIters) LOAD_STAGE((it + 1) & 1, (size_t)(it + 1) * 32);
        if (it + 1 < kIters)
            asm volatile("cp.async.wait_group 1;" ::: "memory");
        else
            asm volatile("cp.async.wait_group 0;" ::: "memory");
        __syncthreads();

        const char* st = smem + (it & 1) * STAGEB;
        const char* sAh = st;
        const char* sAl = st + MATB;
        const char* sBh = st + 2 * MATB;
        const char* sBl = st + 3 * MATB;

#pragma unroll
        for (int ks = 0; ks < 32; ks += 16) {
            uint32_t ah[4][4], al[4][4], bh[4][2], bl[4][2];
            int kb = (ks + tg * 2) * 2;
#pragma unroll
            for (int mt = 0; mt < 4; mt++) {
                int ro = (warp_m * 64 + mt * 16 + g) * PADB + kb;
                ah[mt][0] = *(const uint32_t*)(sAh + ro);
                ah[mt][1] = *(const uint32_t*)(sAh + ro + 8 * PADB);
                ah[mt][2] = *(const uint32_t*)(sAh + ro + 16);
                ah[mt][3] = *(const uint32_t*)(sAh + ro + 8 * PADB + 16);
                al[mt][0] = *(const uint32_t*)(sAl + ro);
                al[mt][1] = *(const uint32_t*)(sAl + ro + 8 * PADB);
                al[mt][2] = *(const uint32_t*)(sAl + ro + 16);
                al[mt][3] = *(const uint32_t*)(sAl + ro + 8 * PADB + 16);
            }
#pragma unroll
            for (int nt = 0; nt < 4; nt++) {
                int ro = (warp_n * 32 + nt * 8 + g) * PADB + kb;
                bh[nt][0] = *(const uint32_t*)(sBh + ro);
                bh[nt][1] = *(const uint32_t*)(sBh + ro + 16);
                bl[nt][0] = *(const uint32_t*)(sBl + ro);
                bl[nt][1] = *(const uint32_t*)(sBl + ro + 16);
            }
#pragma unroll
            for (int mt = 0; mt < 4; mt++)
#pragma unroll
                for (int nt = 0; nt < 4; nt++) {
                    mma16816(acc[mt][nt], ah[mt], bh[nt]);
                    mma16816(acc[mt][nt], ah[mt], bl[nt]);
                    mma16816(acc[mt][nt], al[mt], bh[nt]);
                }
        }
        __syncthreads();
    }

    // ---- epilogue ----
#pragma unroll
    for (int mt = 0; mt < 4; mt++) {
        int row0 = bm * 128 + warp_m * 64 + mt * 16 + g;
#pragma unroll
        for (int nt = 0; nt < 4; nt++) {
            int col = bn * 128 + warp_n * 32 + nt * 8 + tg * 2;
#pragma unroll
            for (int half = 0; half < 2; half++) {
                int row = row0 + half * 8;
                float2 v = make_float2(acc[mt][nt][half * 2], acc[mt][nt][half * 2 + 1]);
                if (EPI == 1) {
                    const float2 r = *(const float2*)(R + (size_t)row * ldc + col);
                    v.x += r.x; v.y += r.y;
                }
                if (EPI == 2) {
                    const float2 b = *(const float2*)(bias + col);
                    v.x = gelu_new(v.x + b.x); v.y = gelu_new(v.y + b.y);
                }
                if (EPI == 4) {
                    const float2 b = *(const float2*)(bias + col);
                    const float2 r = *(const float2*)(R + (size_t)row * ldc + col);
                    v.x += b.x + r.x; v.y += b.y + r.y;
                }
                *(float2*)(C + (size_t)bz * zStride + (size_t)row * ldc + col) = v;
            }
        }
    }
#undef LOAD_STAGE
}

// ---------------- fp32 -> bf16 hi/lo split ----------------
__global__ void split_kernel(const float* __restrict__ in,
                             __nv_bfloat16* __restrict__ hi, __nv_bfloat16* __restrict__ lo) {
    int i = blockIdx.x * blockDim.x + threadIdx.x;
    float4 v = ((const float4*)in)[i];
    float vv[4] = {v.x, v.y, v.z, v.w};
    __nv_bfloat16 h[4], l[4];
#pragma unroll
    for (int j = 0; j < 4; j++) {
        h[j] = __float2bfloat16(vv[j]);
        l[j] = __float2bfloat16(vv[j] - __bfloat162float(h[j]));
    }
    __nv_bfloat162* hp = (__nv_bfloat162*)hi + 2 * (size_t)i;
    __nv_bfloat162* lp = (__nv_bfloat162*)lo + 2 * (size_t)i;
    __nv_bfloat162 t;
    t.x = h[0]; t.y = h[1]; hp[0] = t;
    t.x = h[2]; t.y = h[3]; hp[1] = t;
    t.x = l[0]; t.y = l[1]; lp[0] = t;
    t.x = l[2]; t.y = l[3]; lp[1] = t;
}

// ---------------- weight transpose + split: W[K,N] fp32 -> Wt[N,K] bf16 hi/lo ----------------
__global__ void convT_kernel(const float* __restrict__ W,
                             __nv_bfloat16* __restrict__ Wh, __nv_bfloat16* __restrict__ Wl,
                             int K, int N) {
    __shared__ float t[32][33];
    int nb = blockIdx.x * 32, kb = blockIdx.y * 32;
    int tx = threadIdx.x, ty = threadIdx.y;
#pragma unroll
    for (int j = 0; j < 32; j += 8)
        t[ty + j][tx] = W[(size_t)(kb + ty + j) * N + nb + tx];
    __syncthreads();
#pragma unroll
    for (int j = 0; j < 32; j += 8) {
        float v = t[tx][ty + j];
        __nv_bfloat16 h = __float2bfloat16(v);
        __nv_bfloat16 l = __float2bfloat16(v - __bfloat162float(h));
        size_t o = (size_t)(nb + ty + j) * K + kb + tx;
        Wh[o] = h; Wl[o] = l;
    }
}

// ---------------- head reduce: sum split-K partials + bias + relu ----------------
__global__ void head_reduce(const float* __restrict__ parts, const float* __restrict__ bias,
                            float* __restrict__ out) {
    int i = blockIdx.x * blockDim.x + threadIdx.x;
    float s = bias[i & (OUT_ - 1)];
#pragma unroll
    for (int z = 0; z < 16; z++) s += parts[(size_t)z * (B_ * OUT_) + i];
    out[i] = fmaxf(s, 0.f);
}

// ---------------- embed: [B,C,7,7] -> [B,S,D] + pos ----------------
__global__ void embed_kernel(const float* __restrict__ x, const float* __restrict__ pos) {
    __shared__ float tile[64][S_ + 1];
    int b = blockIdx.y;
    int d0 = blockIdx.x * 64;
    int tid = threadIdx.x;
    for (int idx = tid; idx < 64 * S_; idx += 256) {
        int dr = idx / S_, s = idx % S_;
        tile[dr][s] = x[(size_t)(b * C_ + d0 + dr) * S_ + s];
    }
    __syncthreads();
    for (int idx = tid; idx < S_ * 64; idx += 256) {
        int s = idx >> 6, dr = idx & 63;
        g_h[(size_t)(b * S_ + s) * D_ + d0 + dr] = tile[dr][s] + pos[s * D_ + d0 + dr];
    }
}

// ---------------- layernorm ----------------
__global__ void ln_kernel(const float* __restrict__ in, float* __restrict__ out,
                          const float* __restrict__ sc, const float* __restrict__ bi) {
    int row = blockIdx.x;
    const float* p = in + (size_t)row * D_;
    int tid = threadIdx.x;
    float v[4];
    float s = 0.f, ss = 0.f;
#pragma unroll
    for (int i = 0; i < 4; i++) {
        float t = p[tid + i * 256];
        v[i] = t; s += t; ss += t * t;
    }
    __shared__ float rs[8], rss[8];
    int lane = tid & 31, w = tid >> 5;
#pragma unroll
    for (int o = 16; o; o >>= 1) {
        s  += __shfl_xor_sync(0xffffffffu, s,  o);
        ss += __shfl_xor_sync(0xffffffffu, ss, o);
    }
    if (lane == 0) { rs[w] = s; rss[w] = ss; }
    __syncthreads();
    if (tid < 32) {
        float s2  = (tid < 8) ? rs[tid]  : 0.f;
        float ss2 = (tid < 8) ? rss[tid] : 0.f;
#pragma unroll
        for (int o = 4; o; o >>= 1) {
            s2  += __shfl_xor_sync(0xffffffffu, s2,  o);
            ss2 += __shfl_xor_sync(0xffffffffu, ss2, o);
        }
        if (tid == 0) { rs[0] = s2; rss[0] = ss2; }
    }
    __syncthreads();
    float mean = rs[0] * (1.f / 1024.f);
    float var  = rss[0] * (1.f / 1024.f) - mean * mean;
    float inv  = rsqrtf(var + 1e-5f);
#pragma unroll
    for (int i = 0; i < 4; i++) {
        int d = tid + i * 256;
        out[(size_t)row * D_ + d] = (v[i] - mean) * inv * sc[d] + bi[d];
    }
}

// ---------------- fused attention: one block per (b, head) ----------------
__global__ void attn_kernel() {
    int bh = blockIdx.x;
    int b  = bh >> 1;
    int hh = bh & 1;
    __shared__ float qs[S_ * 65];
    __shared__ float ks[S_ * 65];
    __shared__ float sc[S_ * 50];
    int tid = threadIdx.x;

    int qidx[10], kidx[10];
    float acc[10];
#pragma unroll
    for (int j = 0; j < 10; j++) {
        int p = tid + j * 256;
        acc[j] = 0.f;
        qidx[j] = (p < 2401) ? (p / 49) : 0;
        kidx[j] = (p < 2401) ? (p % 49) : 0;
    }
    const size_t base = (size_t)b * S_ * D_ + hh * HD_;

    for (int c = 0; c < 8; c++) {
        for (int idx = tid; idx < S_ * 64; idx += 256) {
            int r = idx >> 6, d = idx & 63;
            qs[r * 65 + d] = g_q[base + (size_t)r * D_ + c * 64 + d];
            ks[r * 65 + d] = g_k[base + (size_t)r * D_ + c * 64 + d];
        }
        __syncthreads();
#pragma unroll
        for (int j = 0; j < 10; j++) {
            if (tid + j * 256 < 2401) {
                const float* qp = &qs[qidx[j] * 65];
                const float* kp = &ks[kidx[j] * 65];
                float s = 0.f;
#pragma unroll
                for (int d = 0; d < 64; d++) s += qp[d] * kp[d];
                acc[j] += s;
            }
        }
        __syncthreads();
    }

    const float scale = 0.044194173824159216f;
#pragma unroll
    for (int j = 0; j < 10; j++)
        if (tid + j * 256 < 2401) sc[qidx[j] * 50 + kidx[j]] = acc[j] * scale;
    __syncthreads();

    if (tid < S_) {
        float mx = -1e30f;
        for (int k = 0; k < S_; k++) mx = fmaxf(mx, sc[tid * 50 + k]);
        float sum = 0.f;
        for (int k = 0; k < S_; k++) {
            float e = __expf(sc[tid * 50 + k] - mx);
            sc[tid * 50 + k] = e; sum += e;
        }
        float inv = 1.f / sum;
        for (int k = 0; k < S_; k++) sc[tid * 50 + k] *= inv;
    }
    __syncthreads();

    for (int c = 0; c < 8; c++) {
        for (int idx = tid; idx < S_ * 64; idx += 256) {
            int r = idx >> 6, d = idx & 63;
            ks[r * 65 + d] = g_v[base + (size_t)r * D_ + c * 64 + d];
        }
        __syncthreads();
        for (int idx = tid; idx < S_ * 64; idx += 256) {
            int q = idx >> 6, d = idx & 63;
            float s = 0.f;
#pragma unroll
            for (int k = 0; k < S_; k++) s += sc[q * 50 + k] * ks[k * 65 + d];
            g_hn[base + (size_t)q * D_ + c * 64 + d] = s;
        }
        __syncthreads();
    }
}

// ---------------- host orchestration ----------------
extern "C" void kernel_launch(void* const* d_in, const int* in_sizes, int n_in,
                              void* d_out, int out_size) {
    (void)in_sizes; (void)n_in; (void)out_size;
    const float* x      = (const float*)d_in[0];
    const float* pos    = (const float*)d_in[1];
    const float* ln1_s  = (const float*)d_in[2];
    const float* ln1_b  = (const float*)d_in[3];
    const float* wq     = (const float*)d_in[4];
    const float* wk     = (const float*)d_in[5];
    const float* wv     = (const float*)d_in[6];
    const float* wo     = (const float*)d_in[7];
    const float* ln2_s  = (const float*)d_in[8];
    const float* ln2_b  = (const float*)d_in[9];
    const float* w1     = (const float*)d_in[10];
    const float* b1     = (const float*)d_in[11];
    const float* w2     = (const float*)d_in[12];
    const float* b2     = (const float*)d_in[13];
    const float* lnf_s  = (const float*)d_in[14];
    const float* lnf_b  = (const float*)d_in[15];
    const float* head_w = (const float*)d_in[16];
    const float* head_b = (const float*)d_in[17];
    float* out = (float*)d_out;

    float *pH, *pHn, *pQ, *pK, *pV, *pPart;
    __nv_bfloat16 *pAh, *pAl, *pWh, *pWl, *pHWh, *pHWl;
    cudaGetSymbolAddress((void**)&pH,   g_h);
    cudaGetSymbolAddress((void**)&pHn,  g_hn);
    cudaGetSymbolAddress((void**)&pQ,   g_q);
    cudaGetSymbolAddress((void**)&pK,   g_k);
    cudaGetSymbolAddress((void**)&pV,   g_v);
    cudaGetSymbolAddress((void**)&pAh,  g_ah);
    cudaGetSymbolAddress((void**)&pAl,  g_al);
    cudaGetSymbolAddress((void**)&pWh,  g_wh);
    cudaGetSymbolAddress((void**)&pWl,  g_wl);
    cudaGetSymbolAddress((void**)&pHWh, g_hwh);
    cudaGetSymbolAddress((void**)&pHWl, g_hwl);
    cudaGetSymbolAddress((void**)&pPart, g_part);

    cudaFuncSetAttribute(mma_gemm<0>, cudaFuncAttributeMaxDynamicSharedMemorySize, SMEM_GEMM);
    cudaFuncSetAttribute(mma_gemm<1>, cudaFuncAttributeMaxDynamicSharedMemorySize, SMEM_GEMM);
    cudaFuncSetAttribute(mma_gemm<2>, cudaFuncAttributeMaxDynamicSharedMemorySize, SMEM_GEMM);
    cudaFuncSetAttribute(mma_gemm<4>, cudaFuncAttributeMaxDynamicSharedMemorySize, SMEM_GEMM);

    const int WSZ = D_ * D_;
    const dim3 gBig(8, 98, 1);
    const dim3 cblk(32, 8);
    const int NSPLIT = M_ * D_ / 1024;

    // ---- weight transpose + split ----
    for (int i = 0; i < L_; i++) {
        convT_kernel<<<dim3(32, 32), cblk>>>(wq + (size_t)i * WSZ, pWh + (size_t)(i * 6 + 0) * WSZ, pWl + (size_t)(i * 6 + 0) * WSZ, D_, D_);
        convT_kernel<<<dim3(32, 32), cblk>>>(wk + (size_t)i * WSZ, pWh + (size_t)(i * 6 + 1) * WSZ, pWl + (size_t)(i * 6 + 1) * WSZ, D_, D_);
        convT_kernel<<<dim3(32, 32), cblk>>>(wv + (size_t)i * WSZ, pWh + (size_t)(i * 6 + 2) * WSZ, pWl + (size_t)(i * 6 + 2) * WSZ, D_, D_);
        convT_kernel<<<dim3(32, 32), cblk>>>(wo + (size_t)i * WSZ, pWh + (size_t)(i * 6 + 3) * WSZ, pWl + (size_t)(i * 6 + 3) * WSZ, D_, D_);
        convT_kernel<<<dim3(32, 32), cblk>>>(w1 + (size_t)i * WSZ, pWh + (size_t)(i * 6 + 4) * WSZ, pWl + (size_t)(i * 6 + 4) * WSZ, D_, D_);
        convT_kernel<<<dim3(32, 32), cblk>>>(w2 + (size_t)i * WSZ, pWh + (size_t)(i * 6 + 5) * WSZ, pWl + (size_t)(i * 6 + 5) * WSZ, D_, D_);
    }
    convT_kernel<<<dim3(32, KHEAD / 32), cblk>>>(head_w, pHWh, pHWl, KHEAD, OUT_);

    embed_kernel<<<dim3(D_ / 64, B_), 256>>>(x, pos);

    for (int i = 0; i < L_; i++) {
        const __nv_bfloat16* Wh = pWh + (size_t)i * 6 * WSZ;
        const __nv_bfloat16* Wl = pWl + (size_t)i * 6 * WSZ;
        ln_kernel<<<M_, 256>>>(pH, pHn, ln1_s + i * D_, ln1_b + i * D_);
        split_kernel<<<NSPLIT, 256>>>(pHn, pAh, pAl);
        mma_gemm<0><<<gBig, 256, SMEM_GEMM>>>(pAh, pAl, Wh + 0 * WSZ, Wl + 0 * WSZ, nullptr, nullptr, pQ, D_, 32, D_, 0);
        mma_gemm<0><<<gBig, 256, SMEM_GEMM>>>(pAh, pAl, Wh + 1 * WSZ, Wl + 1 * WSZ, nullptr, nullptr, pK, D_, 32, D_, 0);
        mma_gemm<0><<<gBig, 256, SMEM_GEMM>>>(pAh, pAl, Wh + 2 * WSZ, Wl + 2 * WSZ, nullptr, nullptr, pV, D_, 32, D_, 0);
        attn_kernel<<<B_ * H_, 256>>>();
        split_kernel<<<NSPLIT, 256>>>(pHn, pAh, pAl);
        mma_gemm<1><<<gBig, 256, SMEM_GEMM>>>(pAh, pAl, Wh + 3 * WSZ, Wl + 3 * WSZ, nullptr, pH, pH, D_, 32, D_, 0);
        ln_kernel<<<M_, 256>>>(pH, pHn, ln2_s + i * D_, ln2_b + i * D_);
        split_kernel<<<NSPLIT, 256>>>(pHn, pAh, pAl);
        mma_gemm<2><<<gBig, 256, SMEM_GEMM>>>(pAh, pAl, Wh + 4 * WSZ, Wl + 4 * WSZ, b1 + i * FF_, nullptr, pQ, D_, 32, FF_, 0);
        split_kernel<<<NSPLIT, 256>>>(pQ, pAh, pAl);
        mma_gemm<4><<<gBig, 256, SMEM_GEMM>>>(pAh, pAl, Wh + 5 * WSZ, Wl + 5 * WSZ, b2 + i * D_, pH, pH, FF_, 32, D_, 0);
    }

    ln_kernel<<<M_, 256>>>(pH, pHn, lnf_s, lnf_b);
    split_kernel<<<NSPLIT, 256>>>(pHn, pAh, pAl);

    // head: [256, 50176] @ Wt[1024, 50176]^T, split-K = 16 (98 iters each)
    mma_gemm<0><<<dim3(8, 2, 16), 256, SMEM_GEMM>>>(pAh, pAl, pHWh, pHWl, nullptr, nullptr,
                                                    pPart, KHEAD, 98, OUT_, B_ * OUT_);
    head_reduce<<<B_ * OUT_ / 256, 256>>>(pPart, head_b, out);
}

// round 4
// speedup vs baseline: 2.8483x; 1.0977x over previous
#include <cuda_runtime.h>
#include <cuda_bf16.h>
#include <math.h>
#include <cstdint>

// ---------------- problem constants ----------------
#define B_    256
#define C_    1024
#define S_    49
#define D_    1024
#define L_    2
#define H_    2
#define HD_   512
#define FF_   1024
#define OUT_  1024
#define M_    (B_ * S_)   // 12544 rows
#define KHEAD (S_ * D_)   // 50176

// ---------------- device scratch (no allocs allowed) ----------------
__device__ float g_h [M_ * D_];
__device__ float g_q [M_ * D_];
__device__ float g_k [M_ * D_];
__device__ float g_v [M_ * D_];
__device__ __nv_bfloat16 g_ah[M_ * D_];
__device__ __nv_bfloat16 g_al[M_ * D_];
__device__ __nv_bfloat16 g_bh[M_ * FF_];
__device__ __nv_bfloat16 g_bl[M_ * FF_];
__device__ __nv_bfloat16 g_wh[12 * D_ * D_];
__device__ __nv_bfloat16 g_wl[12 * D_ * D_];
__device__ __nv_bfloat16 g_hwh[OUT_ * KHEAD];
__device__ __nv_bfloat16 g_hwl[OUT_ * KHEAD];
__device__ float g_part[16 * B_ * OUT_];

// ---------------- gelu_new ----------------
__device__ __forceinline__ float gelu_new(float x) {
    float x3 = x * x * x;
    return 0.5f * x * (1.f + tanhf(0.7978845608028654f * (x + 0.044715f * x3)));
}

__device__ __forceinline__ void split2(float v, __nv_bfloat16& h, __nv_bfloat16& l) {
    h = __float2bfloat16(v);
    l = __float2bfloat16(v - __bfloat162float(h));
}

// ================= mma.sync bf16 split GEMM =================
// Tile 128x128x32, 256 threads, warps 2(m) x 4(n), warp tile 64x32, 3-stage cp.async.
// EPI: 0 none, 1 +R, 4 bias+R, 5 bias+gelu -> bf16 hi/lo split
#define PADB   80
#define MATB   (128 * PADB)               // 10240
#define STAGEB (4 * MATB)                 // 40960
#define SMEM_GEMM (3 * STAGEB)            // 122880

__device__ __forceinline__ void mma16816(float* d, const uint32_t* a, const uint32_t* b) {
    asm volatile(
        "mma.sync.aligned.m16n8k16.row.col.f32.bf16.bf16.f32 "
        "{%0,%1,%2,%3}, {%4,%5,%6,%7}, {%8,%9}, {%0,%1,%2,%3};"
        : "+f"(d[0]), "+f"(d[1]), "+f"(d[2]), "+f"(d[3])
        : "r"(a[0]), "r"(a[1]), "r"(a[2]), "r"(a[3]), "r"(b[0]), "r"(b[1]));
}
__device__ __forceinline__ void ldm4(uint32_t* r, uint32_t addr) {
    asm volatile("ldmatrix.sync.aligned.m8n8.x4.shared.b16 {%0,%1,%2,%3}, [%4];"
                 : "=r"(r[0]), "=r"(r[1]), "=r"(r[2]), "=r"(r[3]) : "r"(addr));
}

template<int EPI>
__global__ __launch_bounds__(256, 1) void mma_gemm(
    const __nv_bfloat16* __restrict__ Ah, const __nv_bfloat16* __restrict__ Al,
    const __nv_bfloat16* __restrict__ Bh, const __nv_bfloat16* __restrict__ Bl,
    const float* __restrict__ bias, const float* __restrict__ R, float* __restrict__ C,
    int ld, int kIters, int ldc, int zStride,
    __nv_bfloat16* __restrict__ Ch, __nv_bfloat16* __restrict__ Cl)
{
    extern __shared__ char smem[];
    uint32_t sm0;
    asm("{ .reg .u64 t; cvta.to.shared.u64 t, %1; cvt.u32.u64 %0, t; }" : "=r"(sm0) : "l"(smem));
    int tid = threadIdx.x, wid = tid >> 5, lane = tid & 31;
    int bn = blockIdx.x, bm = blockIdx.y, bz = blockIdx.z;
    size_t kStart = (size_t)bz * kIters * 32;

    // ---- loader: thread -> (matrix, rowb, seg), 8 rows x 16B each ----
    int tmat = tid >> 6;
    int tt = tid & 63;
    int seg = tt & 3;
    int rowb = tt >> 2;
    const __nv_bfloat16* mbase[4] = {
        Ah + (size_t)bm * 128 * ld,
        Al + (size_t)bm * 128 * ld,
        Bh + (size_t)bn * 128 * ld,
        Bl + (size_t)bn * 128 * ld };
    const __nv_bfloat16* gb = mbase[tmat] + (size_t)rowb * ld + kStart + seg * 8;
    uint32_t sdst = sm0 + tmat * MATB + rowb * PADB + seg * 16;
    const size_t rstep = (size_t)16 * ld;

#define LOAD_STAGE(stg, kpos)                                                     \
    {                                                                             \
        const __nv_bfloat16* s = gb + (kpos);                                     \
        uint32_t dd = sdst + (stg) * STAGEB;                                      \
        _Pragma("unroll")                                                         \
        for (int rr = 0; rr < 8; rr++)                                            \
            asm volatile("cp.async.cg.shared.global [%0], [%1], 16;"              \
                         :: "r"(dd + rr * 16 * PADB), "l"(s + rr * rstep) : "memory"); \
        asm volatile("cp.async.commit_group;" ::: "memory");                      \
    }

    // ---- compute setup ----
    int warp_m = wid >> 2, warp_n = wid & 3;
    int g = lane >> 2, tg = lane & 3;
    int t8 = lane >> 3, tl = lane & 7;
    // ldmatrix per-lane base offsets (within a matrix tile)
    uint32_t aBase = (uint32_t)((warp_m * 64 + (t8 & 1) * 8 + tl) * PADB + (t8 >> 1) * 16);
    uint32_t bBase = (uint32_t)((warp_n * 32 + (t8 >> 1) * 8 + tl) * PADB + (t8 & 1) * 16);

    float acc[4][4][4];
#pragma unroll
    for (int mt = 0; mt < 4; mt++)
#pragma unroll
        for (int nt = 0; nt < 4; nt++)
#pragma unroll
            for (int j = 0; j < 4; j++) acc[mt][nt][j] = 0.f;

    LOAD_STAGE(0, 0);
    if (kIters > 1) LOAD_STAGE(1, 32);

    for (int it = 0; it < kIters; it++) {
        asm volatile("cp.async.wait_group 1;" ::: "memory");
        __syncthreads();
        uint32_t st = sm0 + (it % 3) * STAGEB;

#pragma unroll
        for (int ks = 0; ks < 2; ks++) {
            uint32_t ko = ks * 32;   // 16 elements * 2B
            uint32_t ah[4][4], al[4][4], bh[4][2], bl[4][2];
#pragma unroll
            for (int mt = 0; mt < 4; mt++) {
                uint32_t ra = st + aBase + mt * (16 * PADB) + ko;
                ldm4(ah[mt], ra);
                ldm4(al[mt], ra + MATB);
            }
#pragma unroll
            for (int p = 0; p < 2; p++) {
                uint32_t rb = st + 2 * MATB + bBase + p * (16 * PADB) + ko;
                uint32_t r4[4];
                ldm4(r4, rb);
                bh[2 * p][0] = r4[0]; bh[2 * p][1] = r4[1];
                bh[2 * p + 1][0] = r4[2]; bh[2 * p + 1][1] = r4[3];
                ldm4(r4, rb + MATB);
                bl[2 * p][0] = r4[0]; bl[2 * p][1] = r4[1];
                bl[2 * p + 1][0] = r4[2]; bl[2 * p + 1][1] = r4[3];
            }
#pragma unroll
            for (int mt = 0; mt < 4; mt++)
#pragma unroll
                for (int nt = 0; nt < 4; nt++) {
                    mma16816(acc[mt][nt], ah[mt], bh[nt]);
                    mma16816(acc[mt][nt], ah[mt], bl[nt]);
                    mma16816(acc[mt][nt], al[mt], bh[nt]);
                }
        }
        if (it + 2 < kIters) {
            LOAD_STAGE((it + 2) % 3, (size_t)(it + 2) * 32);
        } else {
            asm volatile("cp.async.commit_group;" ::: "memory");
        }
    }

    // ---- epilogue ----
#pragma unroll
    for (int mt = 0; mt < 4; mt++) {
        int row0 = bm * 128 + warp_m * 64 + mt * 16 + g;
#pragma unroll
        for (int nt = 0; nt < 4; nt++) {
            int col = bn * 128 + warp_n * 32 + nt * 8 + tg * 2;
#pragma unroll
            for (int half = 0; half < 2; half++) {
                int row = row0 + half * 8;
                float2 v = make_float2(acc[mt][nt][half * 2], acc[mt][nt][half * 2 + 1]);
                if (EPI == 1) {
                    const float2 r = *(const float2*)(R + (size_t)row * ldc + col);
                    v.x += r.x; v.y += r.y;
                }
                if (EPI == 4) {
                    const float2 b = *(const float2*)(bias + col);
                    const float2 r = *(const float2*)(R + (size_t)row * ldc + col);
                    v.x += b.x + r.x; v.y += b.y + r.y;
                }
                if (EPI == 5) {
                    const float2 b = *(const float2*)(bias + col);
                    v.x = gelu_new(v.x + b.x); v.y = gelu_new(v.y + b.y);
                    __nv_bfloat162 hh, ll;
                    split2(v.x, hh.x, ll.x);
                    split2(v.y, hh.y, ll.y);
                    *(__nv_bfloat162*)(Ch + (size_t)row * ldc + col) = hh;
                    *(__nv_bfloat162*)(Cl + (size_t)row * ldc + col) = ll;
                } else {
                    *(float2*)(C + (size_t)bz * zStride + (size_t)row * ldc + col) = v;
                }
            }
        }
    }
#undef LOAD_STAGE
}

// ---------------- weight transpose + split ----------------
__global__ void convT_kernel(const float* __restrict__ W,
                             __nv_bfloat16* __restrict__ Wh, __nv_bfloat16* __restrict__ Wl,
                             int K, int N) {
    __shared__ float t[32][33];
    int nb = blockIdx.x * 32, kb = blockIdx.y * 32;
    int tx = threadIdx.x, ty = threadIdx.y;
#pragma unroll
    for (int j = 0; j < 32; j += 8)
        t[ty + j][tx] = W[(size_t)(kb + ty + j) * N + nb + tx];
    __syncthreads();
#pragma unroll
    for (int j = 0; j < 32; j += 8) {
        float v = t[tx][ty + j];
        __nv_bfloat16 h, l;
        split2(v, h, l);
        size_t o = (size_t)(nb + ty + j) * K + kb + tx;
        Wh[o] = h; Wl[o] = l;
    }
}

// ---------------- head reduce ----------------
__global__ void head_reduce(const float* __restrict__ parts, const float* __restrict__ bias,
                            float* __restrict__ out) {
    int i = blockIdx.x * blockDim.x + threadIdx.x;
    float s = bias[i & (OUT_ - 1)];
#pragma unroll
    for (int z = 0; z < 16; z++) s += parts[(size_t)z * (B_ * OUT_) + i];
    out[i] = fmaxf(s, 0.f);
}

// ---------------- embed ----------------
__global__ void embed_kernel(const float* __restrict__ x, const float* __restrict__ pos) {
    __shared__ float tile[64][S_ + 1];
    int b = blockIdx.y;
    int d0 = blockIdx.x * 64;
    int tid = threadIdx.x;
    for (int idx = tid; idx < 64 * S_; idx += 256) {
        int dr = idx / S_, s = idx % S_;
        tile[dr][s] = x[(size_t)(b * C_ + d0 + dr) * S_ + s];
    }
    __syncthreads();
    for (int idx = tid; idx < S_ * 64; idx += 256) {
        int s = idx >> 6, dr = idx & 63;
        g_h[(size_t)(b * S_ + s) * D_ + d0 + dr] = tile[dr][s] + pos[s * D_ + d0 + dr];
    }
}

// ---------------- layernorm (writes bf16 hi/lo split) ----------------
__global__ void ln_split_kernel(const float* __restrict__ in,
                                __nv_bfloat16* __restrict__ oh, __nv_bfloat16* __restrict__ ol,
                                const float* __restrict__ sc, const float* __restrict__ bi) {
    int row = blockIdx.x;
    const float* p = in + (size_t)row * D_;
    int tid = threadIdx.x;
    float v[4];
    float s = 0.f, ss = 0.f;
#pragma unroll
    for (int i = 0; i < 4; i++) {
        float t = p[tid + i * 256];
        v[i] = t; s += t; ss += t * t;
    }
    __shared__ float rs[8], rss[8];
    int lane = tid & 31, w = tid >> 5;
#pragma unroll
    for (int o = 16; o; o >>= 1) {
        s  += __shfl_xor_sync(0xffffffffu, s,  o);
        ss += __shfl_xor_sync(0xffffffffu, ss, o);
    }
    if (lane == 0) { rs[w] = s; rss[w] = ss; }
    __syncthreads();
    if (tid < 32) {
        float s2  = (tid < 8) ? rs[tid]  : 0.f;
        float ss2 = (tid < 8) ? rss[tid] : 0.f;
#pragma unroll
        for (int o = 4; o; o >>= 1) {
            s2  += __shfl_xor_sync(0xffffffffu, s2,  o);
            ss2 += __shfl_xor_sync(0xffffffffu, ss2, o);
        }
        if (tid == 0) { rs[0] = s2; rss[0] = ss2; }
    }
    __syncthreads();
    float mean = rs[0] * (1.f / 1024.f);
    float var  = rss[0] * (1.f / 1024.f) - mean * mean;
    float inv  = rsqrtf(var + 1e-5f);
#pragma unroll
    for (int i = 0; i < 4; i++) {
        int d = tid + i * 256;
        float r = (v[i] - mean) * inv * sc[d] + bi[d];
        __nv_bfloat16 h, l;
        split2(r, h, l);
        oh[(size_t)row * D_ + d] = h;
        ol[(size_t)row * D_ + d] = l;
    }
}

// ---------------- fused attention (writes split ctx to g_ah/g_al) ----------------
__global__ void attn_kernel() {
    int bh = blockIdx.x;
    int b  = bh >> 1;
    int hh = bh & 1;
    __shared__ float qs[S_ * 65];
    __shared__ float ks[S_ * 65];
    __shared__ float sc[S_ * 50];
    int tid = threadIdx.x;

    int qidx[10], kidx[10];
    float acc[10];
#pragma unroll
    for (int j = 0; j < 10; j++) {
        int p = tid + j * 256;
        acc[j] = 0.f;
        qidx[j] = (p < 2401) ? (p / 49) : 0;
        kidx[j] = (p < 2401) ? (p % 49) : 0;
    }
    const size_t base = (size_t)b * S_ * D_ + hh * HD_;

    for (int c = 0; c < 8; c++) {
        for (int idx = tid; idx < S_ * 64; idx += 256) {
            int r = idx >> 6, d = idx & 63;
            qs[r * 65 + d] = g_q[base + (size_t)r * D_ + c * 64 + d];
            ks[r * 65 + d] = g_k[base + (size_t)r * D_ + c * 64 + d];
        }
        __syncthreads();
#pragma unroll
        for (int j = 0; j < 10; j++) {
            if (tid + j * 256 < 2401) {
                const float* qp = &qs[qidx[j] * 65];
                const float* kp = &ks[kidx[j] * 65];
                float s = 0.f;
#pragma unroll
                for (int d = 0; d < 64; d++) s += qp[d] * kp[d];
                acc[j] += s;
            }
        }
        __syncthreads();
    }

    const float scale = 0.044194173824159216f;
#pragma unroll
    for (int j = 0; j < 10; j++)
        if (tid + j * 256 < 2401) sc[qidx[j] * 50 + kidx[j]] = acc[j] * scale;
    __syncthreads();

    if (tid < S_) {
        float mx = -1e30f;
        for (int k = 0; k < S_; k++) mx = fmaxf(mx, sc[tid * 50 + k]);
        float sum = 0.f;
        for (int k = 0; k < S_; k++) {
            float e = __expf(sc[tid * 50 + k] - mx);
            sc[tid * 50 + k] = e; sum += e;
        }
        float inv = 1.f / sum;
        for (int k = 0; k < S_; k++) sc[tid * 50 + k] *= inv;
    }
    __syncthreads();

    for (int c = 0; c < 8; c++) {
        for (int idx = tid; idx < S_ * 64; idx += 256) {
            int r = idx >> 6, d = idx & 63;
            ks[r * 65 + d] = g_v[base + (size_t)r * D_ + c * 64 + d];
        }
        __syncthreads();
        for (int idx = tid; idx < S_ * 64; idx += 256) {
            int q = idx >> 6, d = idx & 63;
            float s = 0.f;
#pragma unroll
            for (int k = 0; k < S_; k++) s += sc[q * 50 + k] * ks[k * 65 + d];
            __nv_bfloat16 h, l;
            split2(s, h, l);
            g_ah[base + (size_t)q * D_ + c * 64 + d] = h;
            g_al[base + (size_t)q * D_ + c * 64 + d] = l;
        }
        __syncthreads();
    }
}

// ---------------- host orchestration ----------------
extern "C" void kernel_launch(void* const* d_in, const int* in_sizes, int n_in,
                              void* d_out, int out_size) {
    (void)in_sizes; (void)n_in; (void)out_size;
    const float* x      = (const float*)d_in[0];
    const float* pos    = (const float*)d_in[1];
    const float* ln1_s  = (const float*)d_in[2];
    const float* ln1_b  = (const float*)d_in[3];
    const float* wq     = (const float*)d_in[4];
    const float* wk     = (const float*)d_in[5];
    const float* wv     = (const float*)d_in[6];
    const float* wo     = (const float*)d_in[7];
    const float* ln2_s  = (const float*)d_in[8];
    const float* ln2_b  = (const float*)d_in[9];
    const float* w1     = (const float*)d_in[10];
    const float* b1     = (const float*)d_in[11];
    const float* w2     = (const float*)d_in[12];
    const float* b2     = (const float*)d_in[13];
    const float* lnf_s  = (const float*)d_in[14];
    const float* lnf_b  = (const float*)d_in[15];
    const float* head_w = (const float*)d_in[16];
    const float* head_b = (const float*)d_in[17];
    float* out = (float*)d_out;

    float *pH, *pQ, *pK, *pV, *pPart;
    __nv_bfloat16 *pAh, *pAl, *pBh, *pBl, *pWh, *pWl, *pHWh, *pHWl;
    cudaGetSymbolAddress((void**)&pH,   g_h);
    cudaGetSymbolAddress((void**)&pQ,   g_q);
    cudaGetSymbolAddress((void**)&pK,   g_k);
    cudaGetSymbolAddress((void**)&pV,   g_v);
    cudaGetSymbolAddress((void**)&pAh,  g_ah);
    cudaGetSymbolAddress((void**)&pAl,  g_al);
    cudaGetSymbolAddress((void**)&pBh,  g_bh);
    cudaGetSymbolAddress((void**)&pBl,  g_bl);
    cudaGetSymbolAddress((void**)&pWh,  g_wh);
    cudaGetSymbolAddress((void**)&pWl,  g_wl);
    cudaGetSymbolAddress((void**)&pHWh, g_hwh);
    cudaGetSymbolAddress((void**)&pHWl, g_hwl);
    cudaGetSymbolAddress((void**)&pPart, g_part);

    cudaFuncSetAttribute(mma_gemm<0>, cudaFuncAttributeMaxDynamicSharedMemorySize, SMEM_GEMM);
    cudaFuncSetAttribute(mma_gemm<1>, cudaFuncAttributeMaxDynamicSharedMemorySize, SMEM_GEMM);
    cudaFuncSetAttribute(mma_gemm<4>, cudaFuncAttributeMaxDynamicSharedMemorySize, SMEM_GEMM);
    cudaFuncSetAttribute(mma_gemm<5>, cudaFuncAttributeMaxDynamicSharedMemorySize, SMEM_GEMM);

    const int WSZ = D_ * D_;
    const dim3 gBig(8, 98, 1);
    const dim3 cblk(32, 8);

    for (int i = 0; i < L_; i++) {
        convT_kernel<<<dim3(32, 32), cblk>>>(wq + (size_t)i * WSZ, pWh + (size_t)(i * 6 + 0) * WSZ, pWl + (size_t)(i * 6 + 0) * WSZ, D_, D_);
        convT_kernel<<<dim3(32, 32), cblk>>>(wk + (size_t)i * WSZ, pWh + (size_t)(i * 6 + 1) * WSZ, pWl + (size_t)(i * 6 + 1) * WSZ, D_, D_);
        convT_kernel<<<dim3(32, 32), cblk>>>(wv + (size_t)i * WSZ, pWh + (size_t)(i * 6 + 2) * WSZ, pWl + (size_t)(i * 6 + 2) * WSZ, D_, D_);
        convT_kernel<<<dim3(32, 32), cblk>>>(wo + (size_t)i * WSZ, pWh + (size_t)(i * 6 + 3) * WSZ, pWl + (size_t)(i * 6 + 3) * WSZ, D_, D_);
        convT_kernel<<<dim3(32, 32), cblk>>>(w1 + (size_t)i * WSZ, pWh + (size_t)(i * 6 + 4) * WSZ, pWl + (size_t)(i * 6 + 4) * WSZ, D_, D_);
        convT_kernel<<<dim3(32, 32), cblk>>>(w2 + (size_t)i * WSZ, pWh + (size_t)(i * 6 + 5) * WSZ, pWl + (size_t)(i * 6 + 5) * WSZ, D_, D_);
    }
    convT_kernel<<<dim3(32, KHEAD / 32), cblk>>>(head_w, pHWh, pHWl, KHEAD, OUT_);

    embed_kernel<<<dim3(D_ / 64, B_), 256>>>(x, pos);

    for (int i = 0; i < L_; i++) {
        const __nv_bfloat16* Wh = pWh + (size_t)i * 6 * WSZ;
        const __nv_bfloat16* Wl = pWl + (size_t)i * 6 * WSZ;
        ln_split_kernel<<<M_, 256>>>(pH, pAh, pAl, ln1_s + i * D_, ln1_b + i * D_);
        mma_gemm<0><<<gBig, 256, SMEM_GEMM>>>(pAh, pAl, Wh + 0 * WSZ, Wl + 0 * WSZ, nullptr, nullptr, pQ, D_, 32, D_, 0, nullptr, nullptr);
        mma_gemm<0><<<gBig, 256, SMEM_GEMM>>>(pAh, pAl, Wh + 1 * WSZ, Wl + 1 * WSZ, nullptr, nullptr, pK, D_, 32, D_, 0, nullptr, nullptr);
        mma_gemm<0><<<gBig, 256, SMEM_GEMM>>>(pAh, pAl, Wh + 2 * WSZ, Wl + 2 * WSZ, nullptr, nullptr, pV, D_, 32, D_, 0, nullptr, nullptr);
        attn_kernel<<<B_ * H_, 256>>>();
        mma_gemm<1><<<gBig, 256, SMEM_GEMM>>>(pAh, pAl, Wh + 3 * WSZ, Wl + 3 * WSZ, nullptr, pH, pH, D_, 32, D_, 0, nullptr, nullptr);
        ln_split_kernel<<<M_, 256>>>(pH, pAh, pAl, ln2_s + i * D_, ln2_b + i * D_);
        mma_gemm<5><<<gBig, 256, SMEM_GEMM>>>(pAh, pAl, Wh + 4 * WSZ, Wl + 4 * WSZ, b1 + i * FF_, nullptr, nullptr, D_, 32, FF_, 0, pBh, pBl);
        mma_gemm<4><<<gBig, 256, SMEM_GEMM>>>(pBh, pBl, Wh + 5 * WSZ, Wl + 5 * WSZ, b2 + i * D_, pH, pH, FF_, 32, D_, 0, nullptr, nullptr);
    }

    ln_split_kernel<<<M_, 256>>>(pH, pAh, pAl, lnf_s, lnf_b);

    // head: [256, 50176] @ Wt[1024, 50176]^T, split-K = 16 (98 iters each)
    mma_gemm<0><<<dim3(8, 2, 16), 256, SMEM_GEMM>>>(pAh, pAl, pHWh, pHWl, nullptr, nullptr,
                                                    pPart, KHEAD, 98, OUT_, B_ * OUT_, nullptr, nullptr);
    head_reduce<<<B_ * OUT_ / 256, 256>>>(pPart, head_b, out);
}

// round 5
// speedup vs baseline: 3.4318x; 1.2049x over previous
#include <cuda_runtime.h>
#include <cuda_bf16.h>
#include <math.h>
#include <cstdint>

// ---------------- problem constants ----------------
#define B_    256
#define C_    1024
#define S_    49
#define D_    1024
#define L_    2
#define H_    2
#define HD_   512
#define FF_   1024
#define OUT_  1024
#define M_    (B_ * S_)   // 12544 rows
#define KHEAD (S_ * D_)   // 50176

// ---------------- device scratch (no allocs allowed) ----------------
__device__ float g_h  [M_ * D_];
__device__ float g_qkv[M_ * 3 * D_];
__device__ __nv_bfloat16 g_ah[M_ * D_];
__device__ __nv_bfloat16 g_al[M_ * D_];
__device__ __nv_bfloat16 g_bh[M_ * FF_];
__device__ __nv_bfloat16 g_bl[M_ * FF_];
__device__ __nv_bfloat16 g_wh[L_ * 6 * D_ * D_];   // per layer: [qkv 1024x3072][wo][w1][w2], K-major
__device__ __nv_bfloat16 g_wl[L_ * 6 * D_ * D_];
__device__ __nv_bfloat16 g_hwh[KHEAD * OUT_];      // head weight [50176,1024] K-major
__device__ __nv_bfloat16 g_hwl[KHEAD * OUT_];
__device__ float g_part[16 * B_ * OUT_];

// ---------------- helpers ----------------
__device__ __forceinline__ float gelu_new(float x) {
    float x3 = x * x * x;
    return 0.5f * x * (1.f + tanhf(0.7978845608028654f * (x + 0.044715f * x3)));
}
__device__ __forceinline__ void split2(float v, __nv_bfloat16& h, __nv_bfloat16& l) {
    h = __float2bfloat16(v);
    l = __float2bfloat16(v - __bfloat162float(h));
}

__device__ __forceinline__ void mma16816(float* d, const uint32_t* a, const uint32_t* b) {
    asm volatile(
        "mma.sync.aligned.m16n8k16.row.col.f32.bf16.bf16.f32 "
        "{%0,%1,%2,%3}, {%4,%5,%6,%7}, {%8,%9}, {%0,%1,%2,%3};"
        : "+f"(d[0]), "+f"(d[1]), "+f"(d[2]), "+f"(d[3])
        : "r"(a[0]), "r"(a[1]), "r"(a[2]), "r"(a[3]), "r"(b[0]), "r"(b[1]));
}
__device__ __forceinline__ void ldm4(uint32_t* r, uint32_t addr) {
    asm volatile("ldmatrix.sync.aligned.m8n8.x4.shared.b16 {%0,%1,%2,%3}, [%4];"
                 : "=r"(r[0]), "=r"(r[1]), "=r"(r[2]), "=r"(r[3]) : "r"(addr));
}
__device__ __forceinline__ void ldm4t(uint32_t* r, uint32_t addr) {
    asm volatile("ldmatrix.sync.aligned.m8n8.x4.trans.shared.b16 {%0,%1,%2,%3}, [%4];"
                 : "=r"(r[0]), "=r"(r[1]), "=r"(r[2]), "=r"(r[3]) : "r"(addr));
}

// ================= mma.sync bf16 split GEMM =================
// CTA tile 256(M) x 128(N) x 32(K), 256 threads, warps 2(m) x 4(n), warp tile 128x32.
// A row-major [rows, ld] bf16 hi/lo. B K-major [K, ldb] bf16 hi/lo (no transpose).
// EPI: 0 none, 1 +R, 4 bias+R, 5 bias+gelu -> bf16 hi/lo split
#define PADA   80                      // A smem row stride (32 bf16 = 64B data)
#define PADB2  272                     // B smem row stride (128 bf16 = 256B data)
#define AMAT   (256 * PADA)            // 20480
#define BMAT   (32 * PADB2)            // 8704
#define BOFF   (2 * AMAT)              // 40960
#define STAGEB (2 * AMAT + 2 * BMAT)   // 58368
#define SMEM_GEMM (3 * STAGEB)         // 175104

template<int EPI>
__global__ __launch_bounds__(256, 1) void mma_gemm(
    const __nv_bfloat16* __restrict__ Ah, const __nv_bfloat16* __restrict__ Al,
    const __nv_bfloat16* __restrict__ Bh, const __nv_bfloat16* __restrict__ Bl,
    const float* __restrict__ bias, const float* __restrict__ R, float* __restrict__ C,
    int ld, int ldb, int kIters, int ldc, int zStride,
    __nv_bfloat16* __restrict__ Ch, __nv_bfloat16* __restrict__ Cl)
{
    extern __shared__ char smem[];
    uint32_t sm0;
    asm("{ .reg .u64 t; cvta.to.shared.u64 t, %1; cvt.u32.u64 %0, t; }" : "=r"(sm0) : "l"(smem));
    int tid = threadIdx.x, wid = tid >> 5, lane = tid & 31;
    int bn = blockIdx.x, bm = blockIdx.y, bz = blockIdx.z;
    size_t kStart = (size_t)bz * kIters * 32;

    // ---- loader: 12 slots/thread. slots 0..2047 = A (2 mats x 256 rows x 4 segs),
    //      slots 2048..3071 = B (2 mats x 32 rows x 16 segs) ----
    const __nv_bfloat16* srcs[12];
    uint32_t dsts[12];
#pragma unroll
    for (int j = 0; j < 12; j++) {
        int slot = tid + j * 256;
        if (j < 8) {
            int mat = slot >> 10;
            int r   = (slot >> 2) & 255;
            int sg  = slot & 3;
            const __nv_bfloat16* base = mat ? Al : Ah;
            srcs[j] = base + (size_t)(bm * 256 + r) * ld + kStart + sg * 8;
            dsts[j] = sm0 + mat * AMAT + r * PADA + sg * 16;
        } else {
            int s2  = slot - 2048;
            int mat = s2 >> 9;
            int r   = (s2 >> 4) & 31;
            int sg  = s2 & 15;
            const __nv_bfloat16* base = mat ? Bl : Bh;
            srcs[j] = base + (size_t)(kStart + r) * ldb + bn * 128 + sg * 8;
            dsts[j] = sm0 + BOFF + mat * BMAT + r * PADB2 + sg * 16;
        }
    }

#define LOAD_STAGE(stg)                                                            \
    {                                                                              \
        _Pragma("unroll")                                                          \
        for (int j = 0; j < 12; j++) {                                             \
            asm volatile("cp.async.cg.shared.global [%0], [%1], 16;"               \
                         :: "r"(dsts[j] + (stg) * STAGEB), "l"(srcs[j]) : "memory"); \
            srcs[j] += (j < 8) ? 32 : (size_t)32 * ldb;                            \
        }                                                                          \
        asm volatile("cp.async.commit_group;" ::: "memory");                       \
    }

    // ---- compute setup ----
    int warp_m = wid >> 2, warp_n = wid & 3;
    int g = lane >> 2, tg = lane & 3;
    int t8 = lane >> 3, tl = lane & 7;
    uint32_t aBase = (uint32_t)((warp_m * 128 + (t8 & 1) * 8 + tl) * PADA + (t8 >> 1) * 16);
    uint32_t bBase = (uint32_t)(((t8 & 1) * 8 + tl) * PADB2 + (warp_n * 32 + (t8 >> 1) * 8) * 2);

    float acc[8][4][4];
#pragma unroll
    for (int mt = 0; mt < 8; mt++)
#pragma unroll
        for (int nt = 0; nt < 4; nt++)
#pragma unroll
            for (int j = 0; j < 4; j++) acc[mt][nt][j] = 0.f;

    LOAD_STAGE(0);
    LOAD_STAGE(1);

    for (int it = 0; it < kIters; it++) {
        asm volatile("cp.async.wait_group 1;" ::: "memory");
        __syncthreads();
        uint32_t st = sm0 + (it % 3) * STAGEB;

#pragma unroll
        for (int ks = 0; ks < 2; ks++) {
            uint32_t bh[4][2], bl[4][2];
#pragma unroll
            for (int p = 0; p < 2; p++) {
                uint32_t rb = st + BOFF + bBase + ks * (16 * PADB2) + p * 32;
                uint32_t r4[4];
                ldm4t(r4, rb);
                bh[2 * p][0] = r4[0]; bh[2 * p][1] = r4[1];
                bh[2 * p + 1][0] = r4[2]; bh[2 * p + 1][1] = r4[3];
                ldm4t(r4, rb + BMAT);
                bl[2 * p][0] = r4[0]; bl[2 * p][1] = r4[1];
                bl[2 * p + 1][0] = r4[2]; bl[2 * p + 1][1] = r4[3];
            }
#pragma unroll
            for (int mt = 0; mt < 8; mt++) {
                uint32_t ra = st + aBase + mt * (16 * PADA) + ks * 32;
                uint32_t ah[4], al[4];
                ldm4(ah, ra);
                ldm4(al, ra + AMAT);
#pragma unroll
                for (int nt = 0; nt < 4; nt++) {
                    mma16816(acc[mt][nt], ah, bh[nt]);
                    mma16816(acc[mt][nt], ah, bl[nt]);
                    mma16816(acc[mt][nt], al, bh[nt]);
                }
            }
        }
        if (it + 2 < kIters) {
            LOAD_STAGE((it + 2) % 3);
        } else {
            asm volatile("cp.async.commit_group;" ::: "memory");
        }
    }

    // ---- epilogue ----
#pragma unroll
    for (int mt = 0; mt < 8; mt++) {
        int row0 = bm * 256 + warp_m * 128 + mt * 16 + g;
#pragma unroll
        for (int nt = 0; nt < 4; nt++) {
            int col = bn * 128 + warp_n * 32 + nt * 8 + tg * 2;
#pragma unroll
            for (int half = 0; half < 2; half++) {
                int row = row0 + half * 8;
                float2 v = make_float2(acc[mt][nt][half * 2], acc[mt][nt][half * 2 + 1]);
                if (EPI == 1) {
                    const float2 r = *(const float2*)(R + (size_t)row * ldc + col);
                    v.x += r.x; v.y += r.y;
                }
                if (EPI == 4) {
                    const float2 b = *(const float2*)(bias + col);
                    const float2 r = *(const float2*)(R + (size_t)row * ldc + col);
                    v.x += b.x + r.x; v.y += b.y + r.y;
                }
                if (EPI == 5) {
                    const float2 b = *(const float2*)(bias + col);
                    v.x = gelu_new(v.x + b.x); v.y = gelu_new(v.y + b.y);
                    __nv_bfloat162 hh, ll;
                    split2(v.x, hh.x, ll.x);
                    split2(v.y, hh.y, ll.y);
                    *(__nv_bfloat162*)(Ch + (size_t)row * ldc + col) = hh;
                    *(__nv_bfloat162*)(Cl + (size_t)row * ldc + col) = ll;
                } else {
                    *(float2*)(C + (size_t)bz * zStride + (size_t)row * ldc + col) = v;
                }
            }
        }
    }
#undef LOAD_STAGE
}

// ---------------- streaming fp32 -> bf16 hi/lo split, optional column remap ----------------
// src [K, 1024] fp32 -> dst [K, Nout] bf16 hi/lo at column offset coloff.
__global__ void convSplit(const float* __restrict__ W,
                          __nv_bfloat16* __restrict__ Wh, __nv_bfloat16* __restrict__ Wl,
                          int Nout, int coloff) {
    size_t gid = (size_t)blockIdx.x * blockDim.x + threadIdx.x;
    size_t idx = gid * 4;
    int k = (int)(idx >> 10);
    int n = (int)(idx & 1023);
    size_t o = (size_t)k * Nout + coloff + n;
    float4 v = *(const float4*)(W + idx);
    __nv_bfloat162 h0, h1, l0, l1;
    split2(v.x, h0.x, l0.x); split2(v.y, h0.y, l0.y);
    split2(v.z, h1.x, l1.x); split2(v.w, h1.y, l1.y);
    *(__nv_bfloat162*)(Wh + o) = h0;
    *(__nv_bfloat162*)(Wh + o + 2) = h1;
    *(__nv_bfloat162*)(Wl + o) = l0;
    *(__nv_bfloat162*)(Wl + o + 2) = l1;
}

// ---------------- head reduce ----------------
__global__ void head_reduce(const float* __restrict__ parts, const float* __restrict__ bias,
                            float* __restrict__ out) {
    int i = blockIdx.x * blockDim.x + threadIdx.x;
    float s = bias[i & (OUT_ - 1)];
#pragma unroll
    for (int z = 0; z < 16; z++) s += parts[(size_t)z * (B_ * OUT_) + i];
    out[i] = fmaxf(s, 0.f);
}

// ---------------- embed ----------------
__global__ void embed_kernel(const float* __restrict__ x, const float* __restrict__ pos) {
    __shared__ float tile[64][S_ + 1];
    int b = blockIdx.y;
    int d0 = blockIdx.x * 64;
    int tid = threadIdx.x;
    for (int idx = tid; idx < 64 * S_; idx += 256) {
        int dr = idx / S_, s = idx % S_;
        tile[dr][s] = x[(size_t)(b * C_ + d0 + dr) * S_ + s];
    }
    __syncthreads();
    for (int idx = tid; idx < S_ * 64; idx += 256) {
        int s = idx >> 6, dr = idx & 63;
        g_h[(size_t)(b * S_ + s) * D_ + d0 + dr] = tile[dr][s] + pos[s * D_ + d0 + dr];
    }
}

// ---------------- layernorm (writes bf16 hi/lo split) ----------------
__global__ void ln_split_kernel(const float* __restrict__ in,
                                __nv_bfloat16* __restrict__ oh, __nv_bfloat16* __restrict__ ol,
                                const float* __restrict__ sc, const float* __restrict__ bi) {
    int row = blockIdx.x;
    const float* p = in + (size_t)row * D_;
    int tid = threadIdx.x;
    float v[4];
    float s = 0.f, ss = 0.f;
#pragma unroll
    for (int i = 0; i < 4; i++) {
        float t = p[tid + i * 256];
        v[i] = t; s += t; ss += t * t;
    }
    __shared__ float rs[8], rss[8];
    int lane = tid & 31, w = tid >> 5;
#pragma unroll
    for (int o = 16; o; o >>= 1) {
        s  += __shfl_xor_sync(0xffffffffu, s,  o);
        ss += __shfl_xor_sync(0xffffffffu, ss, o);
    }
    if (lane == 0) { rs[w] = s; rss[w] = ss; }
    __syncthreads();
    if (tid < 32) {
        float s2  = (tid < 8) ? rs[tid]  : 0.f;
        float ss2 = (tid < 8) ? rss[tid] : 0.f;
#pragma unroll
        for (int o = 4; o; o >>= 1) {
            s2  += __shfl_xor_sync(0xffffffffu, s2,  o);
            ss2 += __shfl_xor_sync(0xffffffffu, ss2, o);
        }
        if (tid == 0) { rs[0] = s2; rss[0] = ss2; }
    }
    __syncthreads();
    float mean = rs[0] * (1.f / 1024.f);
    float var  = rss[0] * (1.f / 1024.f) - mean * mean;
    float inv  = rsqrtf(var + 1e-5f);
#pragma unroll
    for (int i = 0; i < 4; i++) {
        int d = tid + i * 256;
        float r = (v[i] - mean) * inv * sc[d] + bi[d];
        __nv_bfloat16 h, l;
        split2(r, h, l);
        oh[(size_t)row * D_ + d] = h;
        ol[(size_t)row * D_ + d] = l;
    }
}

// ---------------- fused attention: reads g_qkv [M,3072], writes split ctx ----------------
__global__ void attn_kernel() {
    int bh = blockIdx.x;
    int b  = bh >> 1;
    int hh = bh & 1;
    __shared__ float qs[S_ * 65];
    __shared__ float ks[S_ * 65];
    __shared__ float sc[S_ * 50];
    int tid = threadIdx.x;

    int qidx[10], kidx[10];
    float acc[10];
#pragma unroll
    for (int j = 0; j < 10; j++) {
        int p = tid + j * 256;
        acc[j] = 0.f;
        qidx[j] = (p < 2401) ? (p / 49) : 0;
        kidx[j] = (p < 2401) ? (p % 49) : 0;
    }
    const size_t baseQ = (size_t)b * S_ * 3072 + hh * HD_;

    for (int c = 0; c < 8; c++) {
        for (int idx = tid; idx < S_ * 64; idx += 256) {
            int r = idx >> 6, d = idx & 63;
            qs[r * 65 + d] = g_qkv[baseQ + (size_t)r * 3072 + c * 64 + d];
            ks[r * 65 + d] = g_qkv[baseQ + 1024 + (size_t)r * 3072 + c * 64 + d];
        }
        __syncthreads();
#pragma unroll
        for (int j = 0; j < 10; j++) {
            if (tid + j * 256 < 2401) {
                const float* qp = &qs[qidx[j] * 65];
                const float* kp = &ks[kidx[j] * 65];
                float s = 0.f;
#pragma unroll
                for (int d = 0; d < 64; d++) s += qp[d] * kp[d];
                acc[j] += s;
            }
        }
        __syncthreads();
    }

    const float scale = 0.044194173824159216f;
#pragma unroll
    for (int j = 0; j < 10; j++)
        if (tid + j * 256 < 2401) sc[qidx[j] * 50 + kidx[j]] = acc[j] * scale;
    __syncthreads();

    if (tid < S_) {
        float mx = -1e30f;
        for (int k = 0; k < S_; k++) mx = fmaxf(mx, sc[tid * 50 + k]);
        float sum = 0.f;
        for (int k = 0; k < S_; k++) {
            float e = __expf(sc[tid * 50 + k] - mx);
            sc[tid * 50 + k] = e; sum += e;
        }
        float inv = 1.f / sum;
        for (int k = 0; k < S_; k++) sc[tid * 50 + k] *= inv;
    }
    __syncthreads();

    const size_t baseO = (size_t)b * S_ * D_ + hh * HD_;
    for (int c = 0; c < 8; c++) {
        for (int idx = tid; idx < S_ * 64; idx += 256) {
            int r = idx >> 6, d = idx & 63;
            ks[r * 65 + d] = g_qkv[baseQ + 2048 + (size_t)r * 3072 + c * 64 + d];
        }
        __syncthreads();
        for (int idx = tid; idx < S_ * 64; idx += 256) {
            int q = idx >> 6, d = idx & 63;
            float s = 0.f;
#pragma unroll
            for (int k = 0; k < S_; k++) s += sc[q * 50 + k] * ks[k * 65 + d];
            __nv_bfloat16 h, l;
            split2(s, h, l);
            g_ah[baseO + (size_t)q * D_ + c * 64 + d] = h;
            g_al[baseO + (size_t)q * D_ + c * 64 + d] = l;
        }
        __syncthreads();
    }
}

// ---------------- host orchestration ----------------
extern "C" void kernel_launch(void* const* d_in, const int* in_sizes, int n_in,
                              void* d_out, int out_size) {
    (void)in_sizes; (void)n_in; (void)out_size;
    const float* x      = (const float*)d_in[0];
    const float* pos    = (const float*)d_in[1];
    const float* ln1_s  = (const float*)d_in[2];
    const float* ln1_b  = (const float*)d_in[3];
    const float* wq     = (const float*)d_in[4];
    const float* wk     = (const float*)d_in[5];
    const float* wv     = (const float*)d_in[6];
    const float* wo     = (const float*)d_in[7];
    const float* ln2_s  = (const float*)d_in[8];
    const float* ln2_b  = (const float*)d_in[9];
    const float* w1     = (const float*)d_in[10];
    const float* b1     = (const float*)d_in[11];
    const float* w2     = (const float*)d_in[12];
    const float* b2     = (const float*)d_in[13];
    const float* lnf_s  = (const float*)d_in[14];
    const float* lnf_b  = (const float*)d_in[15];
    const float* head_w = (const float*)d_in[16];
    const float* head_b = (const float*)d_in[17];
    float* out = (float*)d_out;

    float *pH, *pQKV, *pPart;
    __nv_bfloat16 *pAh, *pAl, *pBh, *pBl, *pWh, *pWl, *pHWh, *pHWl;
    cudaGetSymbolAddress((void**)&pH,   g_h);
    cudaGetSymbolAddress((void**)&pQKV, g_qkv);
    cudaGetSymbolAddress((void**)&pAh,  g_ah);
    cudaGetSymbolAddress((void**)&pAl,  g_al);
    cudaGetSymbolAddress((void**)&pBh,  g_bh);
    cudaGetSymbolAddress((void**)&pBl,  g_bl);
    cudaGetSymbolAddress((void**)&pWh,  g_wh);
    cudaGetSymbolAddress((void**)&pWl,  g_wl);
    cudaGetSymbolAddress((void**)&pHWh, g_hwh);
    cudaGetSymbolAddress((void**)&pHWl, g_hwl);
    cudaGetSymbolAddress((void**)&pPart, g_part);

    cudaFuncSetAttribute(mma_gemm<0>, cudaFuncAttributeMaxDynamicSharedMemorySize, SMEM_GEMM);
    cudaFuncSetAttribute(mma_gemm<1>, cudaFuncAttributeMaxDynamicSharedMemorySize, SMEM_GEMM);
    cudaFuncSetAttribute(mma_gemm<4>, cudaFuncAttributeMaxDynamicSharedMemorySize, SMEM_GEMM);
    cudaFuncSetAttribute(mma_gemm<5>, cudaFuncAttributeMaxDynamicSharedMemorySize, SMEM_GEMM);

    const size_t LWB = (size_t)6 * D_ * D_;   // per-layer weight elements
    const int CG = D_ * D_ / 1024;            // convSplit grid for 1024x1024 (=1024)

    // ---- weight conversion (no transpose; K-major kept) ----
    for (int i = 0; i < L_; i++) {
        __nv_bfloat16* bh = pWh + i * LWB;
        __nv_bfloat16* bl = pWl + i * LWB;
        convSplit<<<CG, 256>>>(wq + (size_t)i * D_ * D_, bh, bl, 3072, 0);
        convSplit<<<CG, 256>>>(wk + (size_t)i * D_ * D_, bh, bl, 3072, 1024);
        convSplit<<<CG, 256>>>(wv + (size_t)i * D_ * D_, bh, bl, 3072, 2048);
        convSplit<<<CG, 256>>>(wo + (size_t)i * D_ * D_, bh + 3 * (size_t)D_ * D_, bl + 3 * (size_t)D_ * D_, 1024, 0);
        convSplit<<<CG, 256>>>(w1 + (size_t)i * D_ * D_, bh + 4 * (size_t)D_ * D_, bl + 4 * (size_t)D_ * D_, 1024, 0);
        convSplit<<<CG, 256>>>(w2 + (size_t)i * D_ * D_, bh + 5 * (size_t)D_ * D_, bl + 5 * (size_t)D_ * D_, 1024, 0);
    }
    convSplit<<<KHEAD, 256>>>(head_w, pHWh, pHWl, 1024, 0);

    embed_kernel<<<dim3(D_ / 64, B_), 256>>>(x, pos);

    const dim3 gQKV(24, 49);
    const dim3 gStd(8, 49);

    for (int i = 0; i < L_; i++) {
        const __nv_bfloat16* Wh = pWh + i * LWB;
        const __nv_bfloat16* Wl = pWl + i * LWB;
        ln_split_kernel<<<M_, 256>>>(pH, pAh, pAl, ln1_s + i * D_, ln1_b + i * D_);
        mma_gemm<0><<<gQKV, 256, SMEM_GEMM>>>(pAh, pAl, Wh, Wl, nullptr, nullptr, pQKV,
                                              D_, 3072, 32, 3072, 0, nullptr, nullptr);
        attn_kernel<<<B_ * H_, 256>>>();
        mma_gemm<1><<<gStd, 256, SMEM_GEMM>>>(pAh, pAl, Wh + 3 * (size_t)D_ * D_, Wl + 3 * (size_t)D_ * D_,
                                              nullptr, pH, pH, D_, 1024, 32, 1024, 0, nullptr, nullptr);
        ln_split_kernel<<<M_, 256>>>(pH, pAh, pAl, ln2_s + i * D_, ln2_b + i * D_);
        mma_gemm<5><<<gStd, 256, SMEM_GEMM>>>(pAh, pAl, Wh + 4 * (size_t)D_ * D_, Wl + 4 * (size_t)D_ * D_,
                                              b1 + i * FF_, nullptr, nullptr, D_, 1024, 32, 1024, 0, pBh, pBl);
        mma_gemm<4><<<gStd, 256, SMEM_GEMM>>>(pBh, pBl, Wh + 5 * (size_t)D_ * D_, Wl + 5 * (size_t)D_ * D_,
                                              b2 + i * D_, pH, pH, FF_, 1024, 32, 1024, 0, nullptr, nullptr);
    }

    ln_split_kernel<<<M_, 256>>>(pH, pAh, pAl, lnf_s, lnf_b);

    // head: A=[256, 50176] (split buffers viewed as [256, S*D]), B=[50176,1024], split-K=16
    mma_gemm<0><<<dim3(8, 1, 16), 256, SMEM_GEMM>>>(pAh, pAl, pHWh, pHWl, nullptr, nullptr,
                                                    pPart, KHEAD, 1024, 98, 1024, B_ * OUT_,
                                                    nullptr, nullptr);
    head_reduce<<<B_ * OUT_ / 256, 256>>>(pPart, head_b, out);
}